// round 8
// baseline (speedup 1.0000x reference)
#include <cuda_runtime.h>
#include <math.h>
#include <cstdint>

#define Bn 8
#define Tn 2048
#define Cn 1024
#define Hn 256
#define Mn (Bn * Tn)   // 16384

// Scratch (allocation-free rule: __device__ globals)
__device__ float g_Q[Mn * Hn];       // [b][T][H]  (tf32-rounded)
__device__ float g_K[Mn * Hn];       // [b][T][H]  (tf32-rounded)
__device__ float g_V[Mn * Hn];       // [b][T][H]  (tf32-rounded)
__device__ float g_Qp[Mn * Hn];      // Q packed as mma A-fragments (scaled)
__device__ float g_Kp[Mn * Hn];      // K packed as S-GEMM B-fragments
__device__ float g_Vp[Mn * Hn];      // V packed as PV B-fragments
__device__ float g_Wt[3 * Hn * Cn];  // [which][n][k]

// ---------------------------------------------------------------------------
// Helpers
// ---------------------------------------------------------------------------
__device__ __forceinline__ uint32_t smem_u32(const void* p) {
    uint32_t a;
    asm("{ .reg .u64 t; cvta.to.shared.u64 t, %1; cvt.u32.u64 %0, t; }"
        : "=r"(a) : "l"(p));
    return a;
}
__device__ __forceinline__ uint32_t f2tf32(float f) {
    uint32_t u;
    asm("cvt.rna.tf32.f32 %0, %1;" : "=r"(u) : "f"(f));
    return u;
}
__device__ __forceinline__ void cp_async16(uint32_t saddr, const void* g) {
    asm volatile("cp.async.cg.shared.global [%0], [%1], 16;"
                 :: "r"(saddr), "l"(g) : "memory");
}
__device__ __forceinline__ void cp_commit() {
    asm volatile("cp.async.commit_group;" ::: "memory");
}
__device__ __forceinline__ void mma_tf32(float* c, const uint32_t* a, const uint32_t* b) {
    asm volatile(
        "mma.sync.aligned.m16n8k8.row.col.f32.tf32.tf32.f32 "
        "{%0,%1,%2,%3}, {%4,%5,%6,%7}, {%8,%9}, {%0,%1,%2,%3};"
        : "+f"(c[0]), "+f"(c[1]), "+f"(c[2]), "+f"(c[3])
        : "r"(a[0]), "r"(a[1]), "r"(a[2]), "r"(a[3]), "r"(b[0]), "r"(b[1]));
}

// ---------------------------------------------------------------------------
// Transpose W: [K=1024, N=256] -> g_Wt[which][N][K]
// ---------------------------------------------------------------------------
__global__ __launch_bounds__(256)
void transpose_w_kernel(const float* __restrict__ Wq,
                        const float* __restrict__ Wk,
                        const float* __restrict__ Wv) {
    __shared__ float tile[32][33];
    const int which = blockIdx.z;
    const float* W = (which == 0) ? Wq : (which == 1 ? Wk : Wv);
    float* dst = g_Wt + (size_t)which * Hn * Cn;
    const int k0 = blockIdx.x * 32;
    const int n0 = blockIdx.y * 32;
    const int tx = threadIdx.x, ty = threadIdx.y;
    #pragma unroll
    for (int i = 0; i < 4; i++)
        tile[ty + 8 * i][tx] = W[(size_t)(k0 + ty + 8 * i) * Hn + n0 + tx];
    __syncthreads();
    #pragma unroll
    for (int i = 0; i < 4; i++)
        dst[(size_t)(n0 + ty + 8 * i) * Cn + k0 + tx] = tile[tx][ty + 8 * i];
}

// ---------------------------------------------------------------------------
// Projection via mma.sync tf32; outputs tf32-ROUNDED fp32.
// ---------------------------------------------------------------------------
#define AROW 36
#define TILE_F (128 * AROW)
#define TILE_B (TILE_F * 4)
#define PROJ_SMEM (4 * TILE_B)

__global__ __launch_bounds__(256, 2)
void proj_wmma_kernel(const float* __restrict__ x) {
    extern __shared__ char smem[];
    const uint32_t sb = smem_u32(smem);

    const int tid  = threadIdx.x;
    const int warp = tid >> 5, lane = tid & 31;
    const int group = lane >> 2, tig = lane & 3;
    const int wm = warp & 3, wn = warp >> 2;
    const int which = blockIdx.z;
    const int m0 = blockIdx.x * 128, n0 = blockIdx.y * 128;

    const float* A  = x + (size_t)m0 * Cn;
    const float* Bt = g_Wt + (size_t)which * Hn * Cn + (size_t)n0 * Cn;
    float* outp = ((which == 0) ? g_Q : (which == 1 ? g_K : g_V))
                  + (size_t)m0 * Hn + n0;

    const int r0 = tid >> 3;
    const int cc = (tid & 7) * 4;

    auto fill = [&](int t, int bsel) {
        const uint32_t aOff = sb + bsel * TILE_B;
        const uint32_t bOff = sb + 2 * TILE_B + bsel * TILE_B;
        #pragma unroll
        for (int it = 0; it < 4; it++) {
            int row = r0 + 32 * it;
            cp_async16(aOff + (uint32_t)(row * AROW + cc) * 4,
                       A + (size_t)row * Cn + t * 32 + cc);
            cp_async16(bOff + (uint32_t)(row * AROW + cc) * 4,
                       Bt + (size_t)row * Cn + t * 32 + cc);
        }
    };

    float acc[2][8][4];
    #pragma unroll
    for (int mt = 0; mt < 2; mt++)
        #pragma unroll
        for (int nt = 0; nt < 8; nt++)
            #pragma unroll
            for (int q = 0; q < 4; q++) acc[mt][nt][q] = 0.f;

    fill(0, 0);
    cp_commit();

    const int NT = Cn / 32;
    #pragma unroll 1
    for (int t = 0; t < NT; t++) {
        if (t + 1 < NT) {
            fill(t + 1, (t + 1) & 1);
            cp_commit();
            asm volatile("cp.async.wait_group 1;" ::: "memory");
        } else {
            asm volatile("cp.async.wait_group 0;" ::: "memory");
        }
        __syncthreads();

        const float* As = (const float*)(smem + (t & 1) * TILE_B);
        const float* Bs = (const float*)(smem + 2 * TILE_B + (t & 1) * TILE_B);

        #pragma unroll
        for (int k8 = 0; k8 < 32; k8 += 8) {
            uint32_t a[2][4];
            #pragma unroll
            for (int mt = 0; mt < 2; mt++) {
                int m = wm * 32 + mt * 16 + group;
                a[mt][0] = f2tf32(As[m * AROW + k8 + tig]);
                a[mt][1] = f2tf32(As[(m + 8) * AROW + k8 + tig]);
                a[mt][2] = f2tf32(As[m * AROW + k8 + tig + 4]);
                a[mt][3] = f2tf32(As[(m + 8) * AROW + k8 + tig + 4]);
            }
            uint32_t b[8][2];
            #pragma unroll
            for (int nt = 0; nt < 8; nt++) {
                int n = wn * 64 + nt * 8 + group;
                b[nt][0] = f2tf32(Bs[n * AROW + k8 + tig]);
                b[nt][1] = f2tf32(Bs[n * AROW + k8 + tig + 4]);
            }
            #pragma unroll
            for (int mt = 0; mt < 2; mt++)
                #pragma unroll
                for (int nt = 0; nt < 8; nt++)
                    mma_tf32(acc[mt][nt], a[mt], b[nt]);
        }
        __syncthreads();
    }

    #pragma unroll
    for (int mt = 0; mt < 2; mt++) {
        int m = wm * 32 + mt * 16 + group;
        #pragma unroll
        for (int nt = 0; nt < 8; nt++) {
            int col = wn * 64 + nt * 8 + 2 * tig;
            *(float2*)&outp[(size_t)m * Hn + col] =
                make_float2(__uint_as_float(f2tf32(acc[mt][nt][0])),
                            __uint_as_float(f2tf32(acc[mt][nt][1])));
            *(float2*)&outp[(size_t)(m + 8) * Hn + col] =
                make_float2(__uint_as_float(f2tf32(acc[mt][nt][2])),
                            __uint_as_float(f2tf32(acc[mt][nt][3])));
        }
    }
}

// ---------------------------------------------------------------------------
// Pack Q into A-fragment order (scaled by 1/16), per 16-row block.
// Block layout (4096 floats): [k8(32)][lane(32)][4]:
//   {Q[g][k8*8+tig], Q[g+8][k8*8+tig], Q[g][k8*8+tig+4], Q[g+8][k8*8+tig+4]}
// ---------------------------------------------------------------------------
__global__ __launch_bounds__(256)
void pack_q_kernel() {
    __shared__ float vs[32][260];
    const int b   = blockIdx.y;
    const int t0  = blockIdx.x * 32;
    const int tid = threadIdx.x;
    const float* src = g_Q + ((size_t)b * Tn + t0) * Hn;
    float* dst = g_Qp + ((size_t)b * (Tn / 16) + blockIdx.x * 2) * 4096;
    const float scale = 0.0625f;

    #pragma unroll
    for (int it = 0; it < 8; it++) {
        int f = tid + it * 256;
        int r = f >> 6, c4 = (f & 63) * 4;
        float4 v = *(const float4*)&src[(size_t)r * Hn + c4];
        v.x *= scale; v.y *= scale; v.z *= scale; v.w *= scale;
        *(float4*)&vs[r][c4] = v;
    }
    __syncthreads();

    #pragma unroll
    for (int it = 0; it < 8; it++) {
        int f = tid + it * 256;
        int blk = f >> 10, rem = f & 1023;
        int k8 = rem >> 5, lane = rem & 31;
        int g = lane >> 2, t = lane & 3;
        int r0 = blk * 16 + g, r1 = r0 + 8;
        int c = k8 * 8 + t;
        *(float4*)&dst[(size_t)f * 4] =
            make_float4(vs[r0][c], vs[r1][c], vs[r0][c + 4], vs[r1][c + 4]);
    }
}

// ---------------------------------------------------------------------------
// Pack K into S-GEMM B-fragment order, per 32-key block (8192 floats):
// [k8(32)][wn(2)][lane(32)][4]:
//   {K[n0][c], K[n0][c+4], K[n1][c], K[n1][c+4]}, n0=wn*16+g, n1=n0+8, c=k8*8+t
// ---------------------------------------------------------------------------
__global__ __launch_bounds__(256)
void pack_k_kernel() {
    __shared__ float vs[32][260];
    const int b   = blockIdx.y;
    const int t0  = blockIdx.x * 32;
    const int tid = threadIdx.x;
    const float* src = g_K + ((size_t)b * Tn + t0) * Hn;
    float* dst = g_Kp + ((size_t)b * (Tn / 32) + blockIdx.x) * 8192;

    #pragma unroll
    for (int it = 0; it < 8; it++) {
        int f = tid + it * 256;
        int r = f >> 6, c4 = (f & 63) * 4;
        *(float4*)&vs[r][c4] = *(const float4*)&src[(size_t)r * Hn + c4];
    }
    __syncthreads();

    #pragma unroll
    for (int it = 0; it < 8; it++) {
        int f = tid + it * 256;
        int k8 = f >> 6, wn = (f >> 5) & 1, lane = f & 31;
        int g = lane >> 2, t = lane & 3;
        int n0 = wn * 16 + g, n1 = n0 + 8;
        int c = k8 * 8 + t;
        *(float4*)&dst[(size_t)f * 4] =
            make_float4(vs[n0][c], vs[n0][c + 4], vs[n1][c], vs[n1][c + 4]);
    }
}

// ---------------------------------------------------------------------------
// Pack V into PV B-fragment order, per 32-key block (unchanged from R7).
// ---------------------------------------------------------------------------
__global__ __launch_bounds__(256)
void pack_v_kernel() {
    __shared__ float vs[32][260];
    const int b   = blockIdx.y;
    const int t0  = blockIdx.x * 32;
    const int tid = threadIdx.x;
    const float* src = g_V + ((size_t)b * Tn + t0) * Hn;
    float* dst = g_Vp + ((size_t)b * (Tn / 32) + blockIdx.x) * 8192;

    #pragma unroll
    for (int it = 0; it < 8; it++) {
        int f = tid + it * 256;
        int r = f >> 6, c4 = (f & 63) * 4;
        *(float4*)&vs[r][c4] = *(const float4*)&src[(size_t)r * Hn + c4];
    }
    __syncthreads();

    #pragma unroll
    for (int it = 0; it < 8; it++) {
        int f = tid + it * 256;
        int k8i = f >> 9, wn = (f >> 8) & 1, ntp = (f >> 5) & 7, lane = f & 31;
        int group = lane >> 2, tig = lane & 3;
        int k0 = k8i * 8 + tig, k1 = k0 + 4;
        int d0 = wn * 128 + 2 * ntp * 8 + group, d1 = d0 + 8;
        *(float4*)&dst[(size_t)f * 4] =
            make_float4(vs[k0][d0], vs[k1][d0], vs[k0][d1], vs[k1][d1]);
    }
}

// ---------------------------------------------------------------------------
// Causal flash attention, mma.sync tf32, 2 CTAs/SM.
// BM=64, BN=32, 8 warps (wm 0..3 row groups, wn 0..1).
// Q: packed A-fragments via LDG.128 (L2-resident, no smem).
// K: packed B-fragments, double-buffered smem (2x32KB).
// V: packed B-fragments, single smem buffer (32KB); fill issued at end of
//    previous tile, waited just before PV -> hidden under S-GEMM.
// ---------------------------------------------------------------------------
#define KBUF 32768
#define OFF_K0 0
#define OFF_V  (2 * KBUF)                  // 65536
#define OFF_PS (3 * KBUF)                  // 98304
#define PADP 36
#define OFF_RED (OFF_PS + 64 * PADP * 4)   // 107520
#define ATTN_SMEM (OFF_RED + 1024)         // 108544

__global__ __launch_bounds__(256, 2)
void attn_mma_kernel(float* __restrict__ out) {
    extern __shared__ char smem[];
    const uint32_t sb = smem_u32(smem);
    float* Ps = (float*)(smem + OFF_PS);      // [64][36]
    float* redmax = (float*)(smem + OFF_RED); // [2][64]
    float* redsum = redmax + 128;             // [2][64]

    const int b   = blockIdx.y;
    const int m0  = ((int)gridDim.x - 1 - (int)blockIdx.x) * 64;
    const int tid = threadIdx.x;
    const int warp = tid >> 5, lane = tid & 31;
    const int group = lane >> 2, tig = lane & 3;
    const int wm = warp & 3, wn = warp >> 2;

    const float4* Qp4 = (const float4*)g_Qp
        + ((size_t)b * (Tn / 16) + m0 / 16 + wm) * 1024;
    const float* Kpb = g_Kp + (size_t)b * (Tn / 32) * 8192;
    const float* Vpb = g_Vp + (size_t)b * (Tn / 32) * 8192;

    auto fillK = [&](int t, int bs) {
        const uint32_t off = sb + OFF_K0 + bs * KBUF;
        const float* src = Kpb + (size_t)t * 8192;
        #pragma unroll
        for (int it = 0; it < 8; it++) {
            int f = tid + it * 256;
            cp_async16(off + (uint32_t)f * 16, src + (size_t)f * 4);
        }
    };
    auto fillV = [&](int t) {
        const uint32_t off = sb + OFF_V;
        const float* src = Vpb + (size_t)t * 8192;
        #pragma unroll
        for (int it = 0; it < 8; it++) {
            int f = tid + it * 256;
            cp_async16(off + (uint32_t)f * 16, src + (size_t)f * 4);
        }
    };

    fillK(0, 0); cp_commit();
    fillV(0);    cp_commit();

    const int r0 = wm * 16 + group;           // owned rows r0, r0+8
    float m_run0 = -INFINITY, m_run1 = -INFINITY;
    float l_run0 = 0.f, l_run1 = 0.f;
    float o[16][4];
    #pragma unroll
    for (int nt = 0; nt < 16; nt++)
        #pragma unroll
        for (int q = 0; q < 4; q++) o[nt][q] = 0.f;

    const int NT = m0 / 32 + 2;
    #pragma unroll 1
    for (int t = 0; t < NT; t++) {
        const int bs = t & 1;
        if (t + 1 < NT) {
            fillK(t + 1, bs ^ 1);
            cp_commit();
            asm volatile("cp.async.wait_group 2;" ::: "memory");  // K(t) done
        } else {
            asm volatile("cp.async.wait_group 1;" ::: "memory");  // K(t) done
        }
        __syncthreads();

        const float4* Ks4 = (const float4*)(smem + OFF_K0 + bs * KBUF);
        const int kv0 = t * 32;

        // ---- S = Q K^T (2 n-tiles per warp); Q via LDG.128, K via LDS.128 --
        float sacc[2][4];
        #pragma unroll
        for (int nt = 0; nt < 2; nt++)
            #pragma unroll
            for (int q = 0; q < 4; q++) sacc[nt][q] = 0.f;

        #pragma unroll 8
        for (int k8 = 0; k8 < 32; k8++) {
            float4 qa = __ldg(&Qp4[k8 * 32 + lane]);
            float4 kb = Ks4[(k8 * 2 + wn) * 32 + lane];
            uint32_t a[4] = {__float_as_uint(qa.x), __float_as_uint(qa.y),
                             __float_as_uint(qa.z), __float_as_uint(qa.w)};
            uint32_t b0[2] = {__float_as_uint(kb.x), __float_as_uint(kb.y)};
            uint32_t b1[2] = {__float_as_uint(kb.z), __float_as_uint(kb.w)};
            mma_tf32(sacc[0], a, b0);
            mma_tf32(sacc[1], a, b1);
        }

        // ---- causal mask + row max (scale pre-folded into Q) ----
        const int row0 = m0 + r0, row1 = row0 + 8;
        float mx0 = -INFINITY, mx1 = -INFINITY;
        #pragma unroll
        for (int nt = 0; nt < 2; nt++) {
            int cb = kv0 + wn * 16 + nt * 8 + 2 * tig;
            if (cb     > row0) sacc[nt][0] = -INFINITY;
            if (cb + 1 > row0) sacc[nt][1] = -INFINITY;
            if (cb     > row1) sacc[nt][2] = -INFINITY;
            if (cb + 1 > row1) sacc[nt][3] = -INFINITY;
            mx0 = fmaxf(mx0, fmaxf(sacc[nt][0], sacc[nt][1]));
            mx1 = fmaxf(mx1, fmaxf(sacc[nt][2], sacc[nt][3]));
        }
        mx0 = fmaxf(mx0, __shfl_xor_sync(0xffffffffu, mx0, 1));
        mx0 = fmaxf(mx0, __shfl_xor_sync(0xffffffffu, mx0, 2));
        mx1 = fmaxf(mx1, __shfl_xor_sync(0xffffffffu, mx1, 1));
        mx1 = fmaxf(mx1, __shfl_xor_sync(0xffffffffu, mx1, 2));
        if (tig == 0) {
            redmax[wn * 64 + r0]     = mx0;
            redmax[wn * 64 + r0 + 8] = mx1;
        }
        asm volatile("bar.sync %0, 64;" :: "r"(1 + wm) : "memory");
        float mnew0 = fmaxf(m_run0, fmaxf(redmax[r0],     redmax[64 + r0]));
        float mnew1 = fmaxf(m_run1, fmaxf(redmax[r0 + 8], redmax[64 + r0 + 8]));
        float alpha0 = __expf(m_run0 - mnew0), alpha1 = __expf(m_run1 - mnew1);
        m_run0 = mnew0; m_run1 = mnew1;

        // ---- exp, P write (tf32-rounded), partial sums ----
        float ps0 = 0.f, ps1 = 0.f;
        #pragma unroll
        for (int nt = 0; nt < 2; nt++) {
            int cl = wn * 16 + nt * 8 + 2 * tig;
            float e0 = __expf(sacc[nt][0] - mnew0);
            float e1 = __expf(sacc[nt][1] - mnew0);
            float e2 = __expf(sacc[nt][2] - mnew1);
            float e3 = __expf(sacc[nt][3] - mnew1);
            ps0 += e0 + e1; ps1 += e2 + e3;
            *(float2*)&Ps[r0 * PADP + cl] =
                make_float2(__uint_as_float(f2tf32(e0)), __uint_as_float(f2tf32(e1)));
            *(float2*)&Ps[(r0 + 8) * PADP + cl] =
                make_float2(__uint_as_float(f2tf32(e2)), __uint_as_float(f2tf32(e3)));
        }
        ps0 += __shfl_xor_sync(0xffffffffu, ps0, 1);
        ps0 += __shfl_xor_sync(0xffffffffu, ps0, 2);
        ps1 += __shfl_xor_sync(0xffffffffu, ps1, 1);
        ps1 += __shfl_xor_sync(0xffffffffu, ps1, 2);
        if (tig == 0) {
            redsum[wn * 64 + r0]     = ps0;
            redsum[wn * 64 + r0 + 8] = ps1;
        }

        // ---- wait V(t), full-CTA barrier (covers Ps/redsum + V visibility) --
        if (t + 1 < NT) {
            asm volatile("cp.async.wait_group 1;" ::: "memory");
        } else {
            asm volatile("cp.async.wait_group 0;" ::: "memory");
        }
        __syncthreads();

        l_run0 = l_run0 * alpha0 + redsum[r0]     + redsum[64 + r0];
        l_run1 = l_run1 * alpha1 + redsum[r0 + 8] + redsum[64 + r0 + 8];

        // ---- rescale O ----
        #pragma unroll
        for (int nt = 0; nt < 16; nt++) {
            o[nt][0] *= alpha0; o[nt][1] *= alpha0;
            o[nt][2] *= alpha1; o[nt][3] *= alpha1;
        }

        // ---- O += P V (V packed fragments: LDS.128) ----
        const float4* Vp4 = (const float4*)(smem + OFF_V);
        #pragma unroll
        for (int k8i = 0; k8i < 4; k8i++) {
            int k8 = k8i * 8;
            uint32_t a[4];
            a[0] = __float_as_uint(Ps[r0 * PADP + k8 + tig]);
            a[1] = __float_as_uint(Ps[(r0 + 8) * PADP + k8 + tig]);
            a[2] = __float_as_uint(Ps[r0 * PADP + k8 + tig + 4]);
            a[3] = __float_as_uint(Ps[(r0 + 8) * PADP + k8 + tig + 4]);
            #pragma unroll
            for (int ntp = 0; ntp < 8; ntp++) {
                float4 bv = Vp4[((k8i * 2 + wn) * 8 + ntp) * 32 + lane];
                uint32_t b0[2] = {__float_as_uint(bv.x), __float_as_uint(bv.y)};
                uint32_t b1[2] = {__float_as_uint(bv.z), __float_as_uint(bv.w)};
                mma_tf32(o[2 * ntp],     a, b0);
                mma_tf32(o[2 * ntp + 1], a, b1);
            }
        }
        __syncthreads();   // V + K(t) consumed; safe to refill

        if (t + 1 < NT) {
            fillV(t + 1);
            cp_commit();
        }
    }

    // ---- epilogue ----
    float inv0 = 1.f / l_run0, inv1 = 1.f / l_run1;
    float* ob = out + ((size_t)b * Tn + m0) * Hn;
    #pragma unroll
    for (int nt = 0; nt < 16; nt++) {
        int col = wn * 128 + nt * 8 + 2 * tig;
        *(float2*)&ob[(size_t)r0 * Hn + col] =
            make_float2(o[nt][0] * inv0, o[nt][1] * inv0);
        *(float2*)&ob[(size_t)(r0 + 8) * Hn + col] =
            make_float2(o[nt][2] * inv1, o[nt][3] * inv1);
    }
}

extern "C" void kernel_launch(void* const* d_in, const int* in_sizes, int n_in,
                              void* d_out, int out_size) {
    const float* x  = (const float*)d_in[0];
    const float* Wq = (const float*)d_in[1];
    const float* Wk = (const float*)d_in[2];
    const float* Wv = (const float*)d_in[3];
    float* out = (float*)d_out;

    transpose_w_kernel<<<dim3(Cn / 32, Hn / 32, 3), dim3(32, 8)>>>(Wq, Wk, Wv);

    cudaFuncSetAttribute(proj_wmma_kernel,
                         cudaFuncAttributeMaxDynamicSharedMemorySize, PROJ_SMEM);
    proj_wmma_kernel<<<dim3(Mn / 128, Hn / 128, 3), 256, PROJ_SMEM>>>(x);

    pack_q_kernel<<<dim3(Tn / 32, Bn), 256>>>();
    pack_k_kernel<<<dim3(Tn / 32, Bn), 256>>>();
    pack_v_kernel<<<dim3(Tn / 32, Bn), 256>>>();

    cudaFuncSetAttribute(attn_mma_kernel,
                         cudaFuncAttributeMaxDynamicSharedMemorySize, ATTN_SMEM);
    attn_mma_kernel<<<dim3(Tn / 64, Bn), 256, ATTN_SMEM>>>(out);
}

// round 9
// speedup vs baseline: 1.1363x; 1.1363x over previous
#include <cuda_runtime.h>
#include <math.h>
#include <cstdint>

#define Bn 8
#define Tn 2048
#define Cn 1024
#define Hn 256
#define Mn (Bn * Tn)   // 16384

// Scratch (allocation-free rule: __device__ globals)
__device__ float g_Q[Mn * Hn];       // [b][T][H]  (tf32-rounded)
__device__ float g_K[Mn * Hn];       // [b][T][H]  (tf32-rounded)
__device__ float g_V[Mn * Hn];       // [b][T][H]  (tf32-rounded)
__device__ float g_Qp[Mn * Hn];      // Q packed as mma A-fragments (scaled)
__device__ float g_Kp[Mn * Hn];      // K packed as S-GEMM B-fragments
__device__ float g_Vp[Mn * Hn];      // V packed as PV B-fragments
__device__ float g_Wt[3 * Hn * Cn];  // [which][n][k]

// ---------------------------------------------------------------------------
// Helpers
// ---------------------------------------------------------------------------
__device__ __forceinline__ uint32_t smem_u32(const void* p) {
    uint32_t a;
    asm("{ .reg .u64 t; cvta.to.shared.u64 t, %1; cvt.u32.u64 %0, t; }"
        : "=r"(a) : "l"(p));
    return a;
}
__device__ __forceinline__ uint32_t f2tf32(float f) {
    uint32_t u;
    asm("cvt.rna.tf32.f32 %0, %1;" : "=r"(u) : "f"(f));
    return u;
}
__device__ __forceinline__ void cp_async16(uint32_t saddr, const void* g) {
    asm volatile("cp.async.cg.shared.global [%0], [%1], 16;"
                 :: "r"(saddr), "l"(g) : "memory");
}
__device__ __forceinline__ void cp_commit() {
    asm volatile("cp.async.commit_group;" ::: "memory");
}
__device__ __forceinline__ void mma_tf32(float* c, const uint32_t* a, const uint32_t* b) {
    asm volatile(
        "mma.sync.aligned.m16n8k8.row.col.f32.tf32.tf32.f32 "
        "{%0,%1,%2,%3}, {%4,%5,%6,%7}, {%8,%9}, {%0,%1,%2,%3};"
        : "+f"(c[0]), "+f"(c[1]), "+f"(c[2]), "+f"(c[3])
        : "r"(a[0]), "r"(a[1]), "r"(a[2]), "r"(a[3]), "r"(b[0]), "r"(b[1]));
}

// ---------------------------------------------------------------------------
// Transpose W: [K=1024, N=256] -> g_Wt[which][N][K]
// ---------------------------------------------------------------------------
__global__ __launch_bounds__(256)
void transpose_w_kernel(const float* __restrict__ Wq,
                        const float* __restrict__ Wk,
                        const float* __restrict__ Wv) {
    __shared__ float tile[32][33];
    const int which = blockIdx.z;
    const float* W = (which == 0) ? Wq : (which == 1 ? Wk : Wv);
    float* dst = g_Wt + (size_t)which * Hn * Cn;
    const int k0 = blockIdx.x * 32;
    const int n0 = blockIdx.y * 32;
    const int tx = threadIdx.x, ty = threadIdx.y;
    #pragma unroll
    for (int i = 0; i < 4; i++)
        tile[ty + 8 * i][tx] = W[(size_t)(k0 + ty + 8 * i) * Hn + n0 + tx];
    __syncthreads();
    #pragma unroll
    for (int i = 0; i < 4; i++)
        dst[(size_t)(n0 + ty + 8 * i) * Cn + k0 + tx] = tile[tx][ty + 8 * i];
}

// ---------------------------------------------------------------------------
// Projection via mma.sync tf32; outputs tf32-ROUNDED fp32.
// ---------------------------------------------------------------------------
#define AROW 36
#define TILE_F (128 * AROW)
#define TILE_B (TILE_F * 4)
#define PROJ_SMEM (4 * TILE_B)

__global__ __launch_bounds__(256, 2)
void proj_wmma_kernel(const float* __restrict__ x) {
    extern __shared__ char smem[];
    const uint32_t sb = smem_u32(smem);

    const int tid  = threadIdx.x;
    const int warp = tid >> 5, lane = tid & 31;
    const int group = lane >> 2, tig = lane & 3;
    const int wm = warp & 3, wn = warp >> 2;
    const int which = blockIdx.z;
    const int m0 = blockIdx.x * 128, n0 = blockIdx.y * 128;

    const float* A  = x + (size_t)m0 * Cn;
    const float* Bt = g_Wt + (size_t)which * Hn * Cn + (size_t)n0 * Cn;
    float* outp = ((which == 0) ? g_Q : (which == 1 ? g_K : g_V))
                  + (size_t)m0 * Hn + n0;

    const int r0 = tid >> 3;
    const int cc = (tid & 7) * 4;

    auto fill = [&](int t, int bsel) {
        const uint32_t aOff = sb + bsel * TILE_B;
        const uint32_t bOff = sb + 2 * TILE_B + bsel * TILE_B;
        #pragma unroll
        for (int it = 0; it < 4; it++) {
            int row = r0 + 32 * it;
            cp_async16(aOff + (uint32_t)(row * AROW + cc) * 4,
                       A + (size_t)row * Cn + t * 32 + cc);
            cp_async16(bOff + (uint32_t)(row * AROW + cc) * 4,
                       Bt + (size_t)row * Cn + t * 32 + cc);
        }
    };

    float acc[2][8][4];
    #pragma unroll
    for (int mt = 0; mt < 2; mt++)
        #pragma unroll
        for (int nt = 0; nt < 8; nt++)
            #pragma unroll
            for (int q = 0; q < 4; q++) acc[mt][nt][q] = 0.f;

    fill(0, 0);
    cp_commit();

    const int NT = Cn / 32;
    #pragma unroll 1
    for (int t = 0; t < NT; t++) {
        if (t + 1 < NT) {
            fill(t + 1, (t + 1) & 1);
            cp_commit();
            asm volatile("cp.async.wait_group 1;" ::: "memory");
        } else {
            asm volatile("cp.async.wait_group 0;" ::: "memory");
        }
        __syncthreads();

        const float* As = (const float*)(smem + (t & 1) * TILE_B);
        const float* Bs = (const float*)(smem + 2 * TILE_B + (t & 1) * TILE_B);

        #pragma unroll
        for (int k8 = 0; k8 < 32; k8 += 8) {
            uint32_t a[2][4];
            #pragma unroll
            for (int mt = 0; mt < 2; mt++) {
                int m = wm * 32 + mt * 16 + group;
                a[mt][0] = f2tf32(As[m * AROW + k8 + tig]);
                a[mt][1] = f2tf32(As[(m + 8) * AROW + k8 + tig]);
                a[mt][2] = f2tf32(As[m * AROW + k8 + tig + 4]);
                a[mt][3] = f2tf32(As[(m + 8) * AROW + k8 + tig + 4]);
            }
            uint32_t b[8][2];
            #pragma unroll
            for (int nt = 0; nt < 8; nt++) {
                int n = wn * 64 + nt * 8 + group;
                b[nt][0] = f2tf32(Bs[n * AROW + k8 + tig]);
                b[nt][1] = f2tf32(Bs[n * AROW + k8 + tig + 4]);
            }
            #pragma unroll
            for (int mt = 0; mt < 2; mt++)
                #pragma unroll
                for (int nt = 0; nt < 8; nt++)
                    mma_tf32(acc[mt][nt], a[mt], b[nt]);
        }
        __syncthreads();
    }

    #pragma unroll
    for (int mt = 0; mt < 2; mt++) {
        int m = wm * 32 + mt * 16 + group;
        #pragma unroll
        for (int nt = 0; nt < 8; nt++) {
            int col = wn * 64 + nt * 8 + 2 * tig;
            *(float2*)&outp[(size_t)m * Hn + col] =
                make_float2(__uint_as_float(f2tf32(acc[mt][nt][0])),
                            __uint_as_float(f2tf32(acc[mt][nt][1])));
            *(float2*)&outp[(size_t)(m + 8) * Hn + col] =
                make_float2(__uint_as_float(f2tf32(acc[mt][nt][2])),
                            __uint_as_float(f2tf32(acc[mt][nt][3])));
        }
    }
}

// ---------------------------------------------------------------------------
// Pack Q into A-fragment order (scaled by 1/16), per 16-row block.
// Block (4096 floats): [k8(32)][lane(32)][4] =
//   {Q[g][c], Q[g+8][c], Q[g][c+4], Q[g+8][c+4]}, g=lane>>2, c=k8*8+(lane&3)
// ---------------------------------------------------------------------------
__global__ __launch_bounds__(256)
void pack_q_kernel() {
    __shared__ float vs[32][260];
    const int b   = blockIdx.y;
    const int t0  = blockIdx.x * 32;
    const int tid = threadIdx.x;
    const float* src = g_Q + ((size_t)b * Tn + t0) * Hn;
    float* dst = g_Qp + ((size_t)b * (Tn / 16) + blockIdx.x * 2) * 4096;
    const float scale = 0.0625f;

    #pragma unroll
    for (int it = 0; it < 8; it++) {
        int f = tid + it * 256;
        int r = f >> 6, c4 = (f & 63) * 4;
        float4 v = *(const float4*)&src[(size_t)r * Hn + c4];
        v.x *= scale; v.y *= scale; v.z *= scale; v.w *= scale;
        *(float4*)&vs[r][c4] = v;
    }
    __syncthreads();

    #pragma unroll
    for (int it = 0; it < 8; it++) {
        int f = tid + it * 256;
        int blk = f >> 10, rem = f & 1023;
        int k8 = rem >> 5, lane = rem & 31;
        int g = lane >> 2, t = lane & 3;
        int r0 = blk * 16 + g, r1 = r0 + 8;
        int c = k8 * 8 + t;
        *(float4*)&dst[(size_t)f * 4] =
            make_float4(vs[r0][c], vs[r1][c], vs[r0][c + 4], vs[r1][c + 4]);
    }
}

// ---------------------------------------------------------------------------
// Pack K into S-GEMM B-fragment order, per 32-key block (8192 floats):
// [k8(32)][wn(2)][lane(32)][4] =
//   {K[n0][c], K[n0][c+4], K[n1][c], K[n1][c+4]}, n0=wn*16+g, n1=n0+8
// ---------------------------------------------------------------------------
__global__ __launch_bounds__(256)
void pack_k_kernel() {
    __shared__ float vs[32][260];
    const int b   = blockIdx.y;
    const int t0  = blockIdx.x * 32;
    const int tid = threadIdx.x;
    const float* src = g_K + ((size_t)b * Tn + t0) * Hn;
    float* dst = g_Kp + ((size_t)b * (Tn / 32) + blockIdx.x) * 8192;

    #pragma unroll
    for (int it = 0; it < 8; it++) {
        int f = tid + it * 256;
        int r = f >> 6, c4 = (f & 63) * 4;
        *(float4*)&vs[r][c4] = *(const float4*)&src[(size_t)r * Hn + c4];
    }
    __syncthreads();

    #pragma unroll
    for (int it = 0; it < 8; it++) {
        int f = tid + it * 256;
        int k8 = f >> 6, wn = (f >> 5) & 1, lane = f & 31;
        int g = lane >> 2, t = lane & 3;
        int n0 = wn * 16 + g, n1 = n0 + 8;
        int c = k8 * 8 + t;
        *(float4*)&dst[(size_t)f * 4] =
            make_float4(vs[n0][c], vs[n0][c + 4], vs[n1][c], vs[n1][c + 4]);
    }
}

// ---------------------------------------------------------------------------
// Pack V into PV B-fragment order, per 32-key block (validated in R7).
// ---------------------------------------------------------------------------
__global__ __launch_bounds__(256)
void pack_v_kernel() {
    __shared__ float vs[32][260];
    const int b   = blockIdx.y;
    const int t0  = blockIdx.x * 32;
    const int tid = threadIdx.x;
    const float* src = g_V + ((size_t)b * Tn + t0) * Hn;
    float* dst = g_Vp + ((size_t)b * (Tn / 32) + blockIdx.x) * 8192;

    #pragma unroll
    for (int it = 0; it < 8; it++) {
        int f = tid + it * 256;
        int r = f >> 6, c4 = (f & 63) * 4;
        *(float4*)&vs[r][c4] = *(const float4*)&src[(size_t)r * Hn + c4];
    }
    __syncthreads();

    #pragma unroll
    for (int it = 0; it < 8; it++) {
        int f = tid + it * 256;
        int k8i = f >> 9, wn = (f >> 8) & 1, ntp = (f >> 5) & 7, lane = f & 31;
        int group = lane >> 2, tig = lane & 3;
        int k0 = k8i * 8 + tig, k1 = k0 + 4;
        int d0 = wn * 128 + 2 * ntp * 8 + group, d1 = d0 + 8;
        *(float4*)&dst[(size_t)f * 4] =
            make_float4(vs[k0][d0], vs[k1][d0], vs[k0][d1], vs[k1][d1]);
    }
}

// ---------------------------------------------------------------------------
// Causal flash attention, mma.sync tf32, fully fragment-packed smem operands.
// BM=64, BN=32, 8 warps. wm=warp>>1 (row group), wn=warp&1 (col half):
// SMSP partners (w, w+4) land in DIFFERENT wm bar-groups -> decoupled stalls.
// Q: packed A-fragments, staged once (64KB). K,V: packed B-fragments,
// double-buffered (2x32KB each). S: 2 LDS.128 + 2 HMMA per k8.
// ---------------------------------------------------------------------------
#define QP_BYTES 65536
#define KBUF 32768
#define OFF_QP 0
#define OFF_K0 QP_BYTES                     // 65536
#define OFF_V0 (OFF_K0 + 2 * KBUF)          // 131072
#define OFF_PS (OFF_V0 + 2 * KBUF)          // 196608
#define PADP 36
#define OFF_RED (OFF_PS + 64 * PADP * 4)    // 205824
#define ATTN_SMEM (OFF_RED + 1024)          // 206848

__global__ __launch_bounds__(256, 1)
void attn_mma_kernel(float* __restrict__ out) {
    extern __shared__ char smem[];
    const uint32_t sb = smem_u32(smem);
    float* Ps = (float*)(smem + OFF_PS);      // [64][36]
    float* redmax = (float*)(smem + OFF_RED); // [2][64]
    float* redsum = redmax + 128;             // [2][64]

    const int b   = blockIdx.y;
    const int m0  = ((int)gridDim.x - 1 - (int)blockIdx.x) * 64;
    const int tid = threadIdx.x;
    const int warp = tid >> 5, lane = tid & 31;
    const int group = lane >> 2, tig = lane & 3;
    const int wm = warp >> 1, wn = warp & 1;   // SMSP-decoupled bar groups

    const float* Qpb = g_Qp + ((size_t)b * (Tn / 16) + m0 / 16) * 4096;
    const float* Kpb = g_Kp + (size_t)b * (Tn / 32) * 8192;
    const float* Vpb = g_Vp + (size_t)b * (Tn / 32) * 8192;

    auto fillK = [&](int t, int bs) {
        const uint32_t off = sb + OFF_K0 + bs * KBUF;
        const float* src = Kpb + (size_t)t * 8192;
        #pragma unroll
        for (int it = 0; it < 8; it++) {
            int f = tid + it * 256;
            cp_async16(off + (uint32_t)f * 16, src + (size_t)f * 4);
        }
    };
    auto fillV = [&](int t, int bs) {
        const uint32_t off = sb + OFF_V0 + bs * KBUF;
        const float* src = Vpb + (size_t)t * 8192;
        #pragma unroll
        for (int it = 0; it < 8; it++) {
            int f = tid + it * 256;
            cp_async16(off + (uint32_t)f * 16, src + (size_t)f * 4);
        }
    };

    // Stage Q (packed fragments, 4096 float4) + first K/V
    #pragma unroll
    for (int it = 0; it < 16; it++) {
        int f = tid + it * 256;
        cp_async16(sb + OFF_QP + (uint32_t)f * 16, Qpb + (size_t)f * 4);
    }
    fillK(0, 0);
    fillV(0, 0);
    cp_commit();

    const int r0 = wm * 16 + group;            // owned rows r0, r0+8
    float m_run0 = -INFINITY, m_run1 = -INFINITY;
    float l_run0 = 0.f, l_run1 = 0.f;
    float o[16][4];
    #pragma unroll
    for (int nt = 0; nt < 16; nt++)
        #pragma unroll
        for (int q = 0; q < 4; q++) o[nt][q] = 0.f;

    const int NT = m0 / 32 + 2;
    #pragma unroll 1
    for (int t = 0; t < NT; t++) {
        const int bs = t & 1;
        if (t + 1 < NT) {
            fillK(t + 1, bs ^ 1);
            fillV(t + 1, bs ^ 1);
            cp_commit();
            asm volatile("cp.async.wait_group 1;" ::: "memory");
        } else {
            asm volatile("cp.async.wait_group 0;" ::: "memory");
        }
        __syncthreads();

        const float4* Qw  = (const float4*)(smem + OFF_QP) + wm * 1024;
        const float4* Ks4 = (const float4*)(smem + OFF_K0 + bs * KBUF);
        const float4* Vp4 = (const float4*)(smem + OFF_V0 + bs * KBUF);
        const int kv0 = t * 32;

        // ---- S = Q K^T: 2 LDS.128 + 2 HMMA per k8 ----
        float sacc[2][4];
        #pragma unroll
        for (int nt = 0; nt < 2; nt++)
            #pragma unroll
            for (int q = 0; q < 4; q++) sacc[nt][q] = 0.f;

        #pragma unroll 8
        for (int k8 = 0; k8 < 32; k8++) {
            float4 qa = Qw[k8 * 32 + lane];
            float4 kb = Ks4[(k8 * 2 + wn) * 32 + lane];
            uint32_t a[4] = {__float_as_uint(qa.x), __float_as_uint(qa.y),
                             __float_as_uint(qa.z), __float_as_uint(qa.w)};
            uint32_t b0[2] = {__float_as_uint(kb.x), __float_as_uint(kb.y)};
            uint32_t b1[2] = {__float_as_uint(kb.z), __float_as_uint(kb.w)};
            mma_tf32(sacc[0], a, b0);
            mma_tf32(sacc[1], a, b1);
        }

        // ---- causal mask + row max (scale pre-folded into Q) ----
        const int row0 = m0 + r0, row1 = row0 + 8;
        float mx0 = -INFINITY, mx1 = -INFINITY;
        #pragma unroll
        for (int nt = 0; nt < 2; nt++) {
            int cb = kv0 + wn * 16 + nt * 8 + 2 * tig;
            if (cb     > row0) sacc[nt][0] = -INFINITY;
            if (cb + 1 > row0) sacc[nt][1] = -INFINITY;
            if (cb     > row1) sacc[nt][2] = -INFINITY;
            if (cb + 1 > row1) sacc[nt][3] = -INFINITY;
            mx0 = fmaxf(mx0, fmaxf(sacc[nt][0], sacc[nt][1]));
            mx1 = fmaxf(mx1, fmaxf(sacc[nt][2], sacc[nt][3]));
        }
        mx0 = fmaxf(mx0, __shfl_xor_sync(0xffffffffu, mx0, 1));
        mx0 = fmaxf(mx0, __shfl_xor_sync(0xffffffffu, mx0, 2));
        mx1 = fmaxf(mx1, __shfl_xor_sync(0xffffffffu, mx1, 1));
        mx1 = fmaxf(mx1, __shfl_xor_sync(0xffffffffu, mx1, 2));
        if (tig == 0) {
            redmax[wn * 64 + r0]     = mx0;
            redmax[wn * 64 + r0 + 8] = mx1;
        }
        asm volatile("bar.sync %0, 64;" :: "r"(1 + wm) : "memory");
        float mnew0 = fmaxf(m_run0, fmaxf(redmax[r0],     redmax[64 + r0]));
        float mnew1 = fmaxf(m_run1, fmaxf(redmax[r0 + 8], redmax[64 + r0 + 8]));
        float alpha0 = __expf(m_run0 - mnew0), alpha1 = __expf(m_run1 - mnew1);
        m_run0 = mnew0; m_run1 = mnew1;

        // ---- exp, P write (tf32-rounded), partial sums ----
        float ps0 = 0.f, ps1 = 0.f;
        #pragma unroll
        for (int nt = 0; nt < 2; nt++) {
            int cl = wn * 16 + nt * 8 + 2 * tig;
            float e0 = __expf(sacc[nt][0] - mnew0);
            float e1 = __expf(sacc[nt][1] - mnew0);
            float e2 = __expf(sacc[nt][2] - mnew1);
            float e3 = __expf(sacc[nt][3] - mnew1);
            ps0 += e0 + e1; ps1 += e2 + e3;
            *(float2*)&Ps[r0 * PADP + cl] =
                make_float2(__uint_as_float(f2tf32(e0)), __uint_as_float(f2tf32(e1)));
            *(float2*)&Ps[(r0 + 8) * PADP + cl] =
                make_float2(__uint_as_float(f2tf32(e2)), __uint_as_float(f2tf32(e3)));
        }
        ps0 += __shfl_xor_sync(0xffffffffu, ps0, 1);
        ps0 += __shfl_xor_sync(0xffffffffu, ps0, 2);
        ps1 += __shfl_xor_sync(0xffffffffu, ps1, 1);
        ps1 += __shfl_xor_sync(0xffffffffu, ps1, 2);
        if (tig == 0) {
            redsum[wn * 64 + r0]     = ps0;
            redsum[wn * 64 + r0 + 8] = ps1;
        }
        asm volatile("bar.sync %0, 64;" :: "r"(1 + wm) : "memory");
        l_run0 = l_run0 * alpha0 + redsum[r0]     + redsum[64 + r0];
        l_run1 = l_run1 * alpha1 + redsum[r0 + 8] + redsum[64 + r0 + 8];

        // ---- rescale O ----
        #pragma unroll
        for (int nt = 0; nt < 16; nt++) {
            o[nt][0] *= alpha0; o[nt][1] *= alpha0;
            o[nt][2] *= alpha1; o[nt][3] *= alpha1;
        }

        // ---- O += P V (V packed fragments: LDS.128) ----
        #pragma unroll
        for (int k8i = 0; k8i < 4; k8i++) {
            int k8 = k8i * 8;
            uint32_t a[4];
            a[0] = __float_as_uint(Ps[r0 * PADP + k8 + tig]);
            a[1] = __float_as_uint(Ps[(r0 + 8) * PADP + k8 + tig]);
            a[2] = __float_as_uint(Ps[r0 * PADP + k8 + tig + 4]);
            a[3] = __float_as_uint(Ps[(r0 + 8) * PADP + k8 + tig + 4]);
            #pragma unroll
            for (int ntp = 0; ntp < 8; ntp++) {
                float4 bv = Vp4[((k8i * 2 + wn) * 8 + ntp) * 32 + lane];
                uint32_t b0[2] = {__float_as_uint(bv.x), __float_as_uint(bv.y)};
                uint32_t b1[2] = {__float_as_uint(bv.z), __float_as_uint(bv.w)};
                mma_tf32(o[2 * ntp],     a, b0);
                mma_tf32(o[2 * ntp + 1], a, b1);
            }
        }
        __syncthreads();   // buffers + Ps consumed; safe to refill next iter
    }

    // ---- epilogue ----
    float inv0 = 1.f / l_run0, inv1 = 1.f / l_run1;
    float* ob = out + ((size_t)b * Tn + m0) * Hn;
    #pragma unroll
    for (int nt = 0; nt < 16; nt++) {
        int col = wn * 128 + nt * 8 + 2 * tig;
        *(float2*)&ob[(size_t)r0 * Hn + col] =
            make_float2(o[nt][0] * inv0, o[nt][1] * inv0);
        *(float2*)&ob[(size_t)(r0 + 8) * Hn + col] =
            make_float2(o[nt][2] * inv1, o[nt][3] * inv1);
    }
}

extern "C" void kernel_launch(void* const* d_in, const int* in_sizes, int n_in,
                              void* d_out, int out_size) {
    const float* x  = (const float*)d_in[0];
    const float* Wq = (const float*)d_in[1];
    const float* Wk = (const float*)d_in[2];
    const float* Wv = (const float*)d_in[3];
    float* out = (float*)d_out;

    transpose_w_kernel<<<dim3(Cn / 32, Hn / 32, 3), dim3(32, 8)>>>(Wq, Wk, Wv);

    cudaFuncSetAttribute(proj_wmma_kernel,
                         cudaFuncAttributeMaxDynamicSharedMemorySize, PROJ_SMEM);
    proj_wmma_kernel<<<dim3(Mn / 128, Hn / 128, 3), 256, PROJ_SMEM>>>(x);

    pack_q_kernel<<<dim3(Tn / 32, Bn), 256>>>();
    pack_k_kernel<<<dim3(Tn / 32, Bn), 256>>>();
    pack_v_kernel<<<dim3(Tn / 32, Bn), 256>>>();

    cudaFuncSetAttribute(attn_mma_kernel,
                         cudaFuncAttributeMaxDynamicSharedMemorySize, ATTN_SMEM);
    attn_mma_kernel<<<dim3(Tn / 64, Bn), 256, ATTN_SMEM>>>(out);
}

// round 10
// speedup vs baseline: 1.2135x; 1.0679x over previous
#include <cuda_runtime.h>
#include <math.h>
#include <cstdint>

#define Bn 8
#define Tn 2048
#define Cn 1024
#define Hn 256
#define Mn (Bn * Tn)   // 16384

// Scratch (allocation-free rule: __device__ globals)
__device__ float g_Q[Mn * Hn];       // [b][T][H]  (tf32-rounded)
__device__ float g_K[Mn * Hn];       // [b][T][H]  (tf32-rounded)
__device__ float g_V[Mn * Hn];       // [b][T][H]  (tf32-rounded)
__device__ float g_Qp[Mn * Hn];      // Q packed as mma A-fragments (scaled)
__device__ float g_Kp[Mn * Hn];      // K packed as S-GEMM B-fragments
__device__ float g_Vp[Mn * Hn];      // V packed as PV B-fragments
__device__ float g_Wp[3 * Hn * Cn];  // W packed as proj B-fragments (tf32 RNA)

// ---------------------------------------------------------------------------
// Helpers
// ---------------------------------------------------------------------------
__device__ __forceinline__ uint32_t smem_u32(const void* p) {
    uint32_t a;
    asm("{ .reg .u64 t; cvta.to.shared.u64 t, %1; cvt.u32.u64 %0, t; }"
        : "=r"(a) : "l"(p));
    return a;
}
__device__ __forceinline__ uint32_t f2tf32(float f) {
    uint32_t u;
    asm("cvt.rna.tf32.f32 %0, %1;" : "=r"(u) : "f"(f));
    return u;
}
__device__ __forceinline__ void cp_async16(uint32_t saddr, const void* g) {
    asm volatile("cp.async.cg.shared.global [%0], [%1], 16;"
                 :: "r"(saddr), "l"(g) : "memory");
}
__device__ __forceinline__ void cp_commit() {
    asm volatile("cp.async.commit_group;" ::: "memory");
}
__device__ __forceinline__ void mma_tf32(float* c, const uint32_t* a, const uint32_t* b) {
    asm volatile(
        "mma.sync.aligned.m16n8k8.row.col.f32.tf32.tf32.f32 "
        "{%0,%1,%2,%3}, {%4,%5,%6,%7}, {%8,%9}, {%0,%1,%2,%3};"
        : "+f"(c[0]), "+f"(c[1]), "+f"(c[2]), "+f"(c[3])
        : "r"(a[0]), "r"(a[1]), "r"(a[2]), "r"(a[3]), "r"(b[0]), "r"(b[1]));
}

// ---------------------------------------------------------------------------
// Pack W into proj B-fragment order, tf32-rounded (RNA).
// g_Wp layout: [which][n0b(2)][t(32)] blocks of 4096 floats (1024 float4):
//   idx = ((k8*2 + wn)*4 + ntp)*32 + lane,  lane = g*4 + tt
//   float4 = {W[kc][n_a], W[kc+4][n_a], W[kc][n_b], W[kc+4][n_b]}
//   kc = t*32 + k8*8 + tt,  n_a = n0b*128 + wn*64 + ntp*16 + g,  n_b = n_a+8
// ---------------------------------------------------------------------------
__global__ __launch_bounds__(256)
void pack_w_kernel(const float* __restrict__ Wq,
                   const float* __restrict__ Wk,
                   const float* __restrict__ Wv) {
    __shared__ float vs[32][260];
    const int t     = blockIdx.x;       // k-tile 0..31
    const int which = blockIdx.y;
    const int tid   = threadIdx.x;
    const float* W = (which == 0) ? Wq : (which == 1 ? Wk : Wv);

    // Load W rows t*32 .. t*32+31 (32 x 256 floats), coalesced
    #pragma unroll
    for (int it = 0; it < 8; it++) {
        int f = tid + it * 256;
        int r = f >> 6, c4 = (f & 63) * 4;
        *(float4*)&vs[r][c4] = *(const float4*)&W[(size_t)(t * 32 + r) * Hn + c4];
    }
    __syncthreads();

    float* dstw = g_Wp + (size_t)which * 2 * 32 * 4096;
    #pragma unroll
    for (int it = 0; it < 8; it++) {
        int f = tid + it * 256;
        int n0b = f >> 10, rem = f & 1023;
        int k8 = rem >> 8, wn = (rem >> 7) & 1, ntp = (rem >> 5) & 3, lane = rem & 31;
        int g = lane >> 2, tt = lane & 3;
        int kc = k8 * 8 + tt;
        int n_a = n0b * 128 + wn * 64 + ntp * 16 + g, n_b = n_a + 8;
        float* dst = dstw + ((size_t)n0b * 32 + t) * 4096 + (size_t)rem * 4;
        *(float4*)dst = make_float4(
            __uint_as_float(f2tf32(vs[kc][n_a])),
            __uint_as_float(f2tf32(vs[kc + 4][n_a])),
            __uint_as_float(f2tf32(vs[kc][n_b])),
            __uint_as_float(f2tf32(vs[kc + 4][n_b])));
    }
}

// ---------------------------------------------------------------------------
// Projection via mma.sync tf32, B operand pre-packed as fragments.
// CTA 128x128, BK=32, 8 warps (4 M x 2 N); outputs tf32-ROUNDED fp32.
// ---------------------------------------------------------------------------
#define AROW 36
#define ATILE_B (128 * AROW * 4)            // 18432
#define BTILE_B 16384
#define OFF_PA0 0
#define OFF_PA1 ATILE_B
#define OFF_PB0 (2 * ATILE_B)               // 36864
#define OFF_PB1 (2 * ATILE_B + BTILE_B)     // 53248
#define PROJ_SMEM (2 * ATILE_B + 2 * BTILE_B)  // 69632

__global__ __launch_bounds__(256, 2)
void proj_wmma_kernel(const float* __restrict__ x) {
    extern __shared__ char smem[];
    const uint32_t sb = smem_u32(smem);

    const int tid  = threadIdx.x;
    const int warp = tid >> 5, lane = tid & 31;
    const int group = lane >> 2, tig = lane & 3;
    const int wm = warp & 3, wn = warp >> 2;
    const int which = blockIdx.z;
    const int m0 = blockIdx.x * 128;
    const int n0b = blockIdx.y;             // 0 or 1 (128-col block)

    const float* A = x + (size_t)m0 * Cn;
    const float* Bp = g_Wp + (((size_t)which * 2 + n0b) * 32) * 4096;
    float* outp = ((which == 0) ? g_Q : (which == 1 ? g_K : g_V))
                  + (size_t)m0 * Hn + n0b * 128;

    const int r0f = tid >> 3;
    const int ccf = (tid & 7) * 4;

    auto fill = [&](int t, int bsel) {
        const uint32_t aOff = sb + (bsel ? OFF_PA1 : OFF_PA0);
        const uint32_t bOff = sb + (bsel ? OFF_PB1 : OFF_PB0);
        #pragma unroll
        for (int it = 0; it < 4; it++) {
            int row = r0f + 32 * it;
            cp_async16(aOff + (uint32_t)(row * AROW + ccf) * 4,
                       A + (size_t)row * Cn + t * 32 + ccf);
        }
        const float* Bt = Bp + (size_t)t * 4096;
        #pragma unroll
        for (int it = 0; it < 4; it++) {
            int f = tid + it * 256;
            cp_async16(bOff + (uint32_t)f * 16, Bt + (size_t)f * 4);
        }
    };

    float acc[2][8][4];
    #pragma unroll
    for (int mt = 0; mt < 2; mt++)
        #pragma unroll
        for (int nt = 0; nt < 8; nt++)
            #pragma unroll
            for (int q = 0; q < 4; q++) acc[mt][nt][q] = 0.f;

    fill(0, 0);
    cp_commit();

    const int NT = Cn / 32;
    #pragma unroll 1
    for (int t = 0; t < NT; t++) {
        if (t + 1 < NT) {
            fill(t + 1, (t + 1) & 1);
            cp_commit();
            asm volatile("cp.async.wait_group 1;" ::: "memory");
        } else {
            asm volatile("cp.async.wait_group 0;" ::: "memory");
        }
        __syncthreads();

        const float* As = (const float*)(smem + ((t & 1) ? OFF_PA1 : OFF_PA0));
        const float4* Bs4 = (const float4*)(smem + ((t & 1) ? OFF_PB1 : OFF_PB0));

        #pragma unroll
        for (int k8 = 0; k8 < 4; k8++) {
            uint32_t a[2][4];
            #pragma unroll
            for (int mt = 0; mt < 2; mt++) {
                int m = wm * 32 + mt * 16 + group;
                a[mt][0] = f2tf32(As[m * AROW + k8 * 8 + tig]);
                a[mt][1] = f2tf32(As[(m + 8) * AROW + k8 * 8 + tig]);
                a[mt][2] = f2tf32(As[m * AROW + k8 * 8 + tig + 4]);
                a[mt][3] = f2tf32(As[(m + 8) * AROW + k8 * 8 + tig + 4]);
            }
            #pragma unroll
            for (int ntp = 0; ntp < 4; ntp++) {
                float4 bv = Bs4[((k8 * 2 + wn) * 4 + ntp) * 32 + lane];
                uint32_t b0[2] = {__float_as_uint(bv.x), __float_as_uint(bv.y)};
                uint32_t b1[2] = {__float_as_uint(bv.z), __float_as_uint(bv.w)};
                #pragma unroll
                for (int mt = 0; mt < 2; mt++) {
                    mma_tf32(acc[mt][2 * ntp],     a[mt], b0);
                    mma_tf32(acc[mt][2 * ntp + 1], a[mt], b1);
                }
            }
        }
        __syncthreads();
    }

    #pragma unroll
    for (int mt = 0; mt < 2; mt++) {
        int m = wm * 32 + mt * 16 + group;
        #pragma unroll
        for (int nt = 0; nt < 8; nt++) {
            int col = wn * 64 + nt * 8 + 2 * tig;
            *(float2*)&outp[(size_t)m * Hn + col] =
                make_float2(__uint_as_float(f2tf32(acc[mt][nt][0])),
                            __uint_as_float(f2tf32(acc[mt][nt][1])));
            *(float2*)&outp[(size_t)(m + 8) * Hn + col] =
                make_float2(__uint_as_float(f2tf32(acc[mt][nt][2])),
                            __uint_as_float(f2tf32(acc[mt][nt][3])));
        }
    }
}

// ---------------------------------------------------------------------------
// Pack Q into A-fragment order (scaled by 1/16), per 16-row block.
// ---------------------------------------------------------------------------
__global__ __launch_bounds__(256)
void pack_q_kernel() {
    __shared__ float vs[32][260];
    const int b   = blockIdx.y;
    const int t0  = blockIdx.x * 32;
    const int tid = threadIdx.x;
    const float* src = g_Q + ((size_t)b * Tn + t0) * Hn;
    float* dst = g_Qp + ((size_t)b * (Tn / 16) + blockIdx.x * 2) * 4096;
    const float scale = 0.0625f;

    #pragma unroll
    for (int it = 0; it < 8; it++) {
        int f = tid + it * 256;
        int r = f >> 6, c4 = (f & 63) * 4;
        float4 v = *(const float4*)&src[(size_t)r * Hn + c4];
        v.x *= scale; v.y *= scale; v.z *= scale; v.w *= scale;
        *(float4*)&vs[r][c4] = v;
    }
    __syncthreads();

    #pragma unroll
    for (int it = 0; it < 8; it++) {
        int f = tid + it * 256;
        int blk = f >> 10, rem = f & 1023;
        int k8 = rem >> 5, lane = rem & 31;
        int g = lane >> 2, t = lane & 3;
        int r0 = blk * 16 + g, r1 = r0 + 8;
        int c = k8 * 8 + t;
        *(float4*)&dst[(size_t)f * 4] =
            make_float4(vs[r0][c], vs[r1][c], vs[r0][c + 4], vs[r1][c + 4]);
    }
}

// ---------------------------------------------------------------------------
// Pack K into S-GEMM B-fragment order, per 32-key block.
// ---------------------------------------------------------------------------
__global__ __launch_bounds__(256)
void pack_k_kernel() {
    __shared__ float vs[32][260];
    const int b   = blockIdx.y;
    const int t0  = blockIdx.x * 32;
    const int tid = threadIdx.x;
    const float* src = g_K + ((size_t)b * Tn + t0) * Hn;
    float* dst = g_Kp + ((size_t)b * (Tn / 32) + blockIdx.x) * 8192;

    #pragma unroll
    for (int it = 0; it < 8; it++) {
        int f = tid + it * 256;
        int r = f >> 6, c4 = (f & 63) * 4;
        *(float4*)&vs[r][c4] = *(const float4*)&src[(size_t)r * Hn + c4];
    }
    __syncthreads();

    #pragma unroll
    for (int it = 0; it < 8; it++) {
        int f = tid + it * 256;
        int k8 = f >> 6, wn = (f >> 5) & 1, lane = f & 31;
        int g = lane >> 2, t = lane & 3;
        int n0 = wn * 16 + g, n1 = n0 + 8;
        int c = k8 * 8 + t;
        *(float4*)&dst[(size_t)f * 4] =
            make_float4(vs[n0][c], vs[n0][c + 4], vs[n1][c], vs[n1][c + 4]);
    }
}

// ---------------------------------------------------------------------------
// Pack V into PV B-fragment order, per 32-key block.
// ---------------------------------------------------------------------------
__global__ __launch_bounds__(256)
void pack_v_kernel() {
    __shared__ float vs[32][260];
    const int b   = blockIdx.y;
    const int t0  = blockIdx.x * 32;
    const int tid = threadIdx.x;
    const float* src = g_V + ((size_t)b * Tn + t0) * Hn;
    float* dst = g_Vp + ((size_t)b * (Tn / 32) + blockIdx.x) * 8192;

    #pragma unroll
    for (int it = 0; it < 8; it++) {
        int f = tid + it * 256;
        int r = f >> 6, c4 = (f & 63) * 4;
        *(float4*)&vs[r][c4] = *(const float4*)&src[(size_t)r * Hn + c4];
    }
    __syncthreads();

    #pragma unroll
    for (int it = 0; it < 8; it++) {
        int f = tid + it * 256;
        int k8i = f >> 9, wn = (f >> 8) & 1, ntp = (f >> 5) & 7, lane = f & 31;
        int group = lane >> 2, tig = lane & 3;
        int k0 = k8i * 8 + tig, k1 = k0 + 4;
        int d0 = wn * 128 + 2 * ntp * 8 + group, d1 = d0 + 8;
        *(float4*)&dst[(size_t)f * 4] =
            make_float4(vs[k0][d0], vs[k1][d0], vs[k0][d1], vs[k1][d1]);
    }
}

// ---------------------------------------------------------------------------
// Causal flash attention, mma.sync tf32, fully fragment-packed (R9 structure).
// ---------------------------------------------------------------------------
#define QP_BYTES 65536
#define KBUF 32768
#define OFF_QP 0
#define OFF_K0 QP_BYTES
#define OFF_V0 (OFF_K0 + 2 * KBUF)
#define OFF_PS (OFF_V0 + 2 * KBUF)
#define PADP 36
#define OFF_RED (OFF_PS + 64 * PADP * 4)
#define ATTN_SMEM (OFF_RED + 1024)

__global__ __launch_bounds__(256, 1)
void attn_mma_kernel(float* __restrict__ out) {
    extern __shared__ char smem[];
    const uint32_t sb = smem_u32(smem);
    float* Ps = (float*)(smem + OFF_PS);
    float* redmax = (float*)(smem + OFF_RED);
    float* redsum = redmax + 128;

    const int b   = blockIdx.y;
    const int m0  = ((int)gridDim.x - 1 - (int)blockIdx.x) * 64;
    const int tid = threadIdx.x;
    const int warp = tid >> 5, lane = tid & 31;
    const int group = lane >> 2, tig = lane & 3;
    const int wm = warp >> 1, wn = warp & 1;   // SMSP-decoupled bar groups

    const float* Qpb = g_Qp + ((size_t)b * (Tn / 16) + m0 / 16) * 4096;
    const float* Kpb = g_Kp + (size_t)b * (Tn / 32) * 8192;
    const float* Vpb = g_Vp + (size_t)b * (Tn / 32) * 8192;

    auto fillK = [&](int t, int bs) {
        const uint32_t off = sb + OFF_K0 + bs * KBUF;
        const float* src = Kpb + (size_t)t * 8192;
        #pragma unroll
        for (int it = 0; it < 8; it++) {
            int f = tid + it * 256;
            cp_async16(off + (uint32_t)f * 16, src + (size_t)f * 4);
        }
    };
    auto fillV = [&](int t, int bs) {
        const uint32_t off = sb + OFF_V0 + bs * KBUF;
        const float* src = Vpb + (size_t)t * 8192;
        #pragma unroll
        for (int it = 0; it < 8; it++) {
            int f = tid + it * 256;
            cp_async16(off + (uint32_t)f * 16, src + (size_t)f * 4);
        }
    };

    #pragma unroll
    for (int it = 0; it < 16; it++) {
        int f = tid + it * 256;
        cp_async16(sb + OFF_QP + (uint32_t)f * 16, Qpb + (size_t)f * 4);
    }
    fillK(0, 0);
    fillV(0, 0);
    cp_commit();

    const int r0 = wm * 16 + group;
    float m_run0 = -INFINITY, m_run1 = -INFINITY;
    float l_run0 = 0.f, l_run1 = 0.f;
    float o[16][4];
    #pragma unroll
    for (int nt = 0; nt < 16; nt++)
        #pragma unroll
        for (int q = 0; q < 4; q++) o[nt][q] = 0.f;

    const int NT = m0 / 32 + 2;
    #pragma unroll 1
    for (int t = 0; t < NT; t++) {
        const int bs = t & 1;
        if (t + 1 < NT) {
            fillK(t + 1, bs ^ 1);
            fillV(t + 1, bs ^ 1);
            cp_commit();
            asm volatile("cp.async.wait_group 1;" ::: "memory");
        } else {
            asm volatile("cp.async.wait_group 0;" ::: "memory");
        }
        __syncthreads();

        const float4* Qw  = (const float4*)(smem + OFF_QP) + wm * 1024;
        const float4* Ks4 = (const float4*)(smem + OFF_K0 + bs * KBUF);
        const float4* Vp4 = (const float4*)(smem + OFF_V0 + bs * KBUF);
        const int kv0 = t * 32;

        float sacc[2][4];
        #pragma unroll
        for (int nt = 0; nt < 2; nt++)
            #pragma unroll
            for (int q = 0; q < 4; q++) sacc[nt][q] = 0.f;

        #pragma unroll 8
        for (int k8 = 0; k8 < 32; k8++) {
            float4 qa = Qw[k8 * 32 + lane];
            float4 kb = Ks4[(k8 * 2 + wn) * 32 + lane];
            uint32_t a[4] = {__float_as_uint(qa.x), __float_as_uint(qa.y),
                             __float_as_uint(qa.z), __float_as_uint(qa.w)};
            uint32_t b0[2] = {__float_as_uint(kb.x), __float_as_uint(kb.y)};
            uint32_t b1[2] = {__float_as_uint(kb.z), __float_as_uint(kb.w)};
            mma_tf32(sacc[0], a, b0);
            mma_tf32(sacc[1], a, b1);
        }

        const int row0 = m0 + r0, row1 = row0 + 8;
        float mx0 = -INFINITY, mx1 = -INFINITY;
        #pragma unroll
        for (int nt = 0; nt < 2; nt++) {
            int cb = kv0 + wn * 16 + nt * 8 + 2 * tig;
            if (cb     > row0) sacc[nt][0] = -INFINITY;
            if (cb + 1 > row0) sacc[nt][1] = -INFINITY;
            if (cb     > row1) sacc[nt][2] = -INFINITY;
            if (cb + 1 > row1) sacc[nt][3] = -INFINITY;
            mx0 = fmaxf(mx0, fmaxf(sacc[nt][0], sacc[nt][1]));
            mx1 = fmaxf(mx1, fmaxf(sacc[nt][2], sacc[nt][3]));
        }
        mx0 = fmaxf(mx0, __shfl_xor_sync(0xffffffffu, mx0, 1));
        mx0 = fmaxf(mx0, __shfl_xor_sync(0xffffffffu, mx0, 2));
        mx1 = fmaxf(mx1, __shfl_xor_sync(0xffffffffu, mx1, 1));
        mx1 = fmaxf(mx1, __shfl_xor_sync(0xffffffffu, mx1, 2));
        if (tig == 0) {
            redmax[wn * 64 + r0]     = mx0;
            redmax[wn * 64 + r0 + 8] = mx1;
        }
        asm volatile("bar.sync %0, 64;" :: "r"(1 + wm) : "memory");
        float mnew0 = fmaxf(m_run0, fmaxf(redmax[r0],     redmax[64 + r0]));
        float mnew1 = fmaxf(m_run1, fmaxf(redmax[r0 + 8], redmax[64 + r0 + 8]));
        float alpha0 = __expf(m_run0 - mnew0), alpha1 = __expf(m_run1 - mnew1);
        m_run0 = mnew0; m_run1 = mnew1;

        float ps0 = 0.f, ps1 = 0.f;
        #pragma unroll
        for (int nt = 0; nt < 2; nt++) {
            int cl = wn * 16 + nt * 8 + 2 * tig;
            float e0 = __expf(sacc[nt][0] - mnew0);
            float e1 = __expf(sacc[nt][1] - mnew0);
            float e2 = __expf(sacc[nt][2] - mnew1);
            float e3 = __expf(sacc[nt][3] - mnew1);
            ps0 += e0 + e1; ps1 += e2 + e3;
            *(float2*)&Ps[r0 * PADP + cl] =
                make_float2(__uint_as_float(f2tf32(e0)), __uint_as_float(f2tf32(e1)));
            *(float2*)&Ps[(r0 + 8) * PADP + cl] =
                make_float2(__uint_as_float(f2tf32(e2)), __uint_as_float(f2tf32(e3)));
        }
        ps0 += __shfl_xor_sync(0xffffffffu, ps0, 1);
        ps0 += __shfl_xor_sync(0xffffffffu, ps0, 2);
        ps1 += __shfl_xor_sync(0xffffffffu, ps1, 1);
        ps1 += __shfl_xor_sync(0xffffffffu, ps1, 2);
        if (tig == 0) {
            redsum[wn * 64 + r0]     = ps0;
            redsum[wn * 64 + r0 + 8] = ps1;
        }
        asm volatile("bar.sync %0, 64;" :: "r"(1 + wm) : "memory");
        l_run0 = l_run0 * alpha0 + redsum[r0]     + redsum[64 + r0];
        l_run1 = l_run1 * alpha1 + redsum[r0 + 8] + redsum[64 + r0 + 8];

        #pragma unroll
        for (int nt = 0; nt < 16; nt++) {
            o[nt][0] *= alpha0; o[nt][1] *= alpha0;
            o[nt][2] *= alpha1; o[nt][3] *= alpha1;
        }

        #pragma unroll
        for (int k8i = 0; k8i < 4; k8i++) {
            int k8 = k8i * 8;
            uint32_t a[4];
            a[0] = __float_as_uint(Ps[r0 * PADP + k8 + tig]);
            a[1] = __float_as_uint(Ps[(r0 + 8) * PADP + k8 + tig]);
            a[2] = __float_as_uint(Ps[r0 * PADP + k8 + tig + 4]);
            a[3] = __float_as_uint(Ps[(r0 + 8) * PADP + k8 + tig + 4]);
            #pragma unroll
            for (int ntp = 0; ntp < 8; ntp++) {
                float4 bv = Vp4[((k8i * 2 + wn) * 8 + ntp) * 32 + lane];
                uint32_t b0[2] = {__float_as_uint(bv.x), __float_as_uint(bv.y)};
                uint32_t b1[2] = {__float_as_uint(bv.z), __float_as_uint(bv.w)};
                mma_tf32(o[2 * ntp],     a, b0);
                mma_tf32(o[2 * ntp + 1], a, b1);
            }
        }
        __syncthreads();
    }

    float inv0 = 1.f / l_run0, inv1 = 1.f / l_run1;
    float* ob = out + ((size_t)b * Tn + m0) * Hn;
    #pragma unroll
    for (int nt = 0; nt < 16; nt++) {
        int col = wn * 128 + nt * 8 + 2 * tig;
        *(float2*)&ob[(size_t)r0 * Hn + col] =
            make_float2(o[nt][0] * inv0, o[nt][1] * inv0);
        *(float2*)&ob[(size_t)(r0 + 8) * Hn + col] =
            make_float2(o[nt][2] * inv1, o[nt][3] * inv1);
    }
}

extern "C" void kernel_launch(void* const* d_in, const int* in_sizes, int n_in,
                              void* d_out, int out_size) {
    const float* x  = (const float*)d_in[0];
    const float* Wq = (const float*)d_in[1];
    const float* Wk = (const float*)d_in[2];
    const float* Wv = (const float*)d_in[3];
    float* out = (float*)d_out;

    pack_w_kernel<<<dim3(32, 3), 256>>>(Wq, Wk, Wv);

    cudaFuncSetAttribute(proj_wmma_kernel,
                         cudaFuncAttributeMaxDynamicSharedMemorySize, PROJ_SMEM);
    proj_wmma_kernel<<<dim3(Mn / 128, 2, 3), 256, PROJ_SMEM>>>(x);

    pack_q_kernel<<<dim3(Tn / 32, Bn), 256>>>();
    pack_k_kernel<<<dim3(Tn / 32, Bn), 256>>>();
    pack_v_kernel<<<dim3(Tn / 32, Bn), 256>>>();

    cudaFuncSetAttribute(attn_mma_kernel,
                         cudaFuncAttributeMaxDynamicSharedMemorySize, ATTN_SMEM);
    attn_mma_kernel<<<dim3(Tn / 64, Bn), 256, ATTN_SMEM>>>(out);
}